// round 2
// baseline (speedup 1.0000x reference)
#include <cuda_runtime.h>
#include <cuda_bf16.h>
#include <cstdint>

// ---------------------------------------------------------------------------
// Problem dims
// ---------------------------------------------------------------------------
#define BATCH   4096
#define IN_DIM  1024
#define OUT_DIM 1024
#define KBIG    4096          // 4 * IN_DIM
#define KEFF    12288         // 3 * KBIG (hi*hi, hi*lo, lo*hi)

// GEMM tiling
#define BM 128
#define BN 128
#define BK 64                 // bf16 -> 128 bytes per row
#define NCHUNK (KEFF / BK)    // 192
#define STAGES 4
#define TILE_A_BYTES (BM * 128)            // 16 KB
#define TILE_B_BYTES (BN * 128)            // 16 KB
#define STAGE_BYTES  (TILE_A_BYTES + TILE_B_BYTES)   // 32 KB
#define SMEM_TOTAL   (STAGES * STAGE_BYTES)          // 128 KB

#define SMEM_SWIZZLE_128B(off) ((off) ^ (((off) >> 3) & 0x70))

// ---------------------------------------------------------------------------
// Device scratch (allocation-free rule: __device__ globals)
// ---------------------------------------------------------------------------
__device__ float          g_coef[BATCH * 4];
__device__ __nv_bfloat16  g_Ah[BATCH * KBIG];         // 32 MB
__device__ __nv_bfloat16  g_Al[BATCH * KBIG];         // 32 MB
__device__ __nv_bfloat16  g_Wh[4 * OUT_DIM * IN_DIM]; // 8 MB
__device__ __nv_bfloat16  g_Wl[4 * OUT_DIM * IN_DIM]; // 8 MB

// ---------------------------------------------------------------------------
// PTX helpers (baseline ISA only — no sm_103a-specific features)
// ---------------------------------------------------------------------------
__device__ __forceinline__ uint32_t smem_to_u32(const void* p) {
    uint32_t a;
    asm("{ .reg .u64 t; cvta.to.shared.u64 t, %1; cvt.u32.u64 %0, t; }"
        : "=r"(a) : "l"(p));
    return a;
}

__device__ __forceinline__ void cp_async16(uint32_t saddr, const void* gaddr) {
    asm volatile("cp.async.cg.shared.global [%0], [%1], 16;"
                 :: "r"(saddr), "l"(gaddr));
}

#define CP_ASYNC_COMMIT() asm volatile("cp.async.commit_group;" ::: "memory")
#define CP_ASYNC_WAIT2()  asm volatile("cp.async.wait_group 2;" ::: "memory")

__device__ __forceinline__ void ldsm_x4(uint32_t (&r)[4], uint32_t addr) {
    asm volatile("ldmatrix.sync.aligned.m8n8.x4.shared.b16 {%0,%1,%2,%3}, [%4];"
                 : "=r"(r[0]), "=r"(r[1]), "=r"(r[2]), "=r"(r[3]) : "r"(addr));
}

__device__ __forceinline__ void mma_16816(float (&d)[4], const uint32_t (&a)[4],
                                          uint32_t b0, uint32_t b1) {
    asm volatile(
        "mma.sync.aligned.m16n8k16.row.col.f32.bf16.bf16.f32 "
        "{%0,%1,%2,%3}, {%4,%5,%6,%7}, {%8,%9}, {%0,%1,%2,%3};"
        : "+f"(d[0]), "+f"(d[1]), "+f"(d[2]), "+f"(d[3])
        : "r"(a[0]), "r"(a[1]), "r"(a[2]), "r"(a[3]), "r"(b0), "r"(b1));
}

// ---------------------------------------------------------------------------
// Kernel 1: spline coefficients (CPI permutation folded in)
//   c_eff[b][j] = coeffs[b][(j - q + 1) & 3]
// ---------------------------------------------------------------------------
__global__ void coef_kernel(const float* __restrict__ phase,
                            const float* __restrict__ basis)
{
    int b = blockIdx.x * blockDim.x + threadIdx.x;
    if (b >= BATCH) return;
    const float HALF_PI = 1.5707963267948966f;
    float r = phase[b] / HALF_PI;
    int q = (int)floorf(r);
    q = min(max(q, 0), 3);
    float t  = r - (float)q;
    float t2 = t * t;
    float t3 = t2 * t;
    float co[4];
#pragma unroll
    for (int k = 0; k < 4; k++)
        co[k] = t3 * basis[k] + t2 * basis[4 + k] + t * basis[8 + k] + basis[12 + k];
#pragma unroll
    for (int j = 0; j < 4; j++)
        g_coef[b * 4 + j] = co[(j - q + 1) & 3];
}

// ---------------------------------------------------------------------------
// Kernel 2: A = c_eff[b,j] * x[b,i], split into bf16 hi/lo
// ---------------------------------------------------------------------------
__device__ __forceinline__ uint32_t pack2bf16(__nv_bfloat16 lo, __nv_bfloat16 hi)
{
    return ((uint32_t)__bfloat16_as_ushort(hi) << 16) |
           (uint32_t)__bfloat16_as_ushort(lo);
}

__device__ __forceinline__ void split1(float a, __nv_bfloat16& h, __nv_bfloat16& l)
{
    h = __float2bfloat16(a);
    l = __float2bfloat16(a - __bfloat162float(h));
}

__global__ void split_a_kernel(const float* __restrict__ x)
{
    int t = blockIdx.x * blockDim.x + threadIdx.x;   // one float4 of x per thread
    int b  = t >> 8;
    int iv = t & 255;
    float4 xv = reinterpret_cast<const float4*>(x)[t];
    float cs[4];
#pragma unroll
    for (int j = 0; j < 4; j++) cs[j] = g_coef[b * 4 + j];
#pragma unroll
    for (int j = 0; j < 4; j++) {
        float a0 = cs[j] * xv.x, a1 = cs[j] * xv.y;
        float a2 = cs[j] * xv.z, a3 = cs[j] * xv.w;
        __nv_bfloat16 h0, h1, h2, h3, l0, l1, l2, l3;
        split1(a0, h0, l0); split1(a1, h1, l1);
        split1(a2, h2, l2); split1(a3, h3, l3);
        size_t base = (size_t)b * KBIG + j * IN_DIM + iv * 4;
        uint2 vh = make_uint2(pack2bf16(h0, h1), pack2bf16(h2, h3));
        uint2 vl = make_uint2(pack2bf16(l0, l1), pack2bf16(l2, l3));
        *reinterpret_cast<uint2*>(g_Ah + base) = vh;
        *reinterpret_cast<uint2*>(g_Al + base) = vl;
    }
}

// ---------------------------------------------------------------------------
// Kernel 3: weights -> bf16 hi/lo
// ---------------------------------------------------------------------------
__global__ void split_w_kernel(const float* __restrict__ w)
{
    int t = blockIdx.x * blockDim.x + threadIdx.x;
    float4 wv = reinterpret_cast<const float4*>(w)[t];
    __nv_bfloat16 h0, h1, h2, h3, l0, l1, l2, l3;
    split1(wv.x, h0, l0); split1(wv.y, h1, l1);
    split1(wv.z, h2, l2); split1(wv.w, h3, l3);
    size_t base = (size_t)t * 4;
    uint2 vh = make_uint2(pack2bf16(h0, h1), pack2bf16(h2, h3));
    uint2 vl = make_uint2(pack2bf16(l0, l1), pack2bf16(l2, l3));
    *reinterpret_cast<uint2*>(g_Wh + base) = vh;
    *reinterpret_cast<uint2*>(g_Wl + base) = vl;
}

// ---------------------------------------------------------------------------
// Kernel 4: mma.sync bf16 GEMM, K_eff = 12288, + rank-4 bias epilogue
//   segment 0: Ah x Wh, segment 1: Ah x Wl, segment 2: Al x Wh
// ---------------------------------------------------------------------------
__device__ __forceinline__ void issue_tile_load(
    uint32_t smem_base, int stage, int ck, int tid, int mBase, int nBase)
{
    const int kk = ck * BK;
    const int s  = kk >> 12;              // 0,1,2
    const int kA = kk & (KBIG - 1);

    const __nv_bfloat16* __restrict__ Asrc = (s < 2) ? g_Ah : g_Al;
    const __nv_bfloat16* __restrict__ Bsrc = (s == 1) ? g_Wl : g_Wh;
    const int j  = kA >> 10;
    const int i0 = kA & (IN_DIM - 1);
    const __nv_bfloat16* __restrict__ Bbase =
        Bsrc + (size_t)j * (OUT_DIM * IN_DIM) + i0;

    const uint32_t sa = smem_base + stage * STAGE_BYTES;
    const uint32_t sb = sa + TILE_A_BYTES;

#pragma unroll
    for (int it = 0; it < 4; it++) {
        int idx = tid + it * 256;
        int row = idx >> 3;
        int cv  = idx & 7;
        const void* g = Asrc + (size_t)(mBase + row) * KBIG + kA + cv * 8;
        cp_async16(sa + SMEM_SWIZZLE_128B(row * 128 + cv * 16), g);
    }
#pragma unroll
    for (int it = 0; it < 4; it++) {
        int idx = tid + it * 256;
        int row = idx >> 3;
        int cv  = idx & 7;
        const void* g = Bbase + (size_t)(nBase + row) * IN_DIM + cv * 8;
        cp_async16(sb + SMEM_SWIZZLE_128B(row * 128 + cv * 16), g);
    }
}

__global__ void __launch_bounds__(256, 1)
gemm_kernel(const float* __restrict__ biases, float* __restrict__ out)
{
    extern __shared__ char smem[];
    const uint32_t smem_base = smem_to_u32(smem);
    const int tid  = threadIdx.x;
    const int wid  = tid >> 5;
    const int lane = tid & 31;
    const int wm   = wid & 1;    // 2 warp rows  (64 rows each)
    const int wn   = wid >> 1;   // 4 warp cols  (32 cols each)

    const int mBase = blockIdx.x * BM;
    const int nBase = blockIdx.y * BN;

    float acc[4][4][4];
#pragma unroll
    for (int i = 0; i < 4; i++)
#pragma unroll
        for (int j = 0; j < 4; j++)
#pragma unroll
            for (int k = 0; k < 4; k++) acc[i][j][k] = 0.f;

    // Per-thread ldmatrix address components (byte offsets before swizzle)
    // A x4: lanes 0-7 rows m+0..7 @k0 | 8-15 rows m+8..15 @k0
    //       16-23 rows m+0..7 @k0+16B | 24-31 rows m+8..15 @k0+16B
    const int a_row = lane & 15;
    const int a_colh = (lane >> 4) * 16;
    // B x4: lanes 0-7 rows n+0..7 @k0 | 8-15 rows n+0..7 @+16B
    //       16-23 rows n+8..15 @k0   | 24-31 rows n+8..15 @+16B
    const int b_row = (lane & 7) + ((lane >> 4) << 3);
    const int b_colh = ((lane >> 3) & 1) * 16;

    // Prologue: fill STAGES-1 stages
#pragma unroll
    for (int s = 0; s < STAGES - 1; s++) {
        issue_tile_load(smem_base, s, s, tid, mBase, nBase);
        CP_ASYNC_COMMIT();
    }

#pragma unroll 1
    for (int ck = 0; ck < NCHUNK; ck++) {
        CP_ASYNC_WAIT2();
        __syncthreads();

        // Issue load for chunk ck+STAGES-1 into stage (ck-1)%STAGES
        {
            int lck = ck + STAGES - 1;
            if (lck < NCHUNK)
                issue_tile_load(smem_base, lck & (STAGES - 1), lck, tid, mBase, nBase);
            CP_ASYNC_COMMIT();
        }

        const uint32_t sa = smem_base + (ck & (STAGES - 1)) * STAGE_BYTES;
        const uint32_t sb = sa + TILE_A_BYTES;

#pragma unroll
        for (int ks = 0; ks < 4; ks++) {        // 4 x k16 within BK=64
            uint32_t afrag[4][4];
#pragma unroll
            for (int mt = 0; mt < 4; mt++) {
                int off = (wm * 64 + mt * 16 + a_row) * 128 + ks * 32 + a_colh;
                ldsm_x4(afrag[mt], sa + SMEM_SWIZZLE_128B(off));
            }
            uint32_t bfrag[4][2];
#pragma unroll
            for (int nt2 = 0; nt2 < 2; nt2++) {
                uint32_t b4[4];
                int off = (wn * 32 + nt2 * 16 + b_row) * 128 + ks * 32 + b_colh;
                ldsm_x4(b4, sb + SMEM_SWIZZLE_128B(off));
                bfrag[nt2 * 2 + 0][0] = b4[0]; bfrag[nt2 * 2 + 0][1] = b4[1];
                bfrag[nt2 * 2 + 1][0] = b4[2]; bfrag[nt2 * 2 + 1][1] = b4[3];
            }
#pragma unroll
            for (int mt = 0; mt < 4; mt++)
#pragma unroll
                for (int nt = 0; nt < 4; nt++)
                    mma_16816(acc[mt][nt], afrag[mt], bfrag[nt][0], bfrag[nt][1]);
        }
    }

    // ---- Epilogue: D += sum_j c_j[b] * bias_j[o] ----
    const int tg = lane >> 2;        // row within 8
    const int tc = (lane & 3) * 2;   // col pair

    float cA[4][4], cB[4][4];        // coefs for rows r0, r0+8 per mt
#pragma unroll
    for (int mt = 0; mt < 4; mt++) {
        int r0 = mBase + wm * 64 + mt * 16 + tg;
#pragma unroll
        for (int j = 0; j < 4; j++) {
            cA[mt][j] = g_coef[r0 * 4 + j];
            cB[mt][j] = g_coef[(r0 + 8) * 4 + j];
        }
    }

#pragma unroll
    for (int nt = 0; nt < 4; nt++) {
        int col = nBase + wn * 32 + nt * 8 + tc;
        float2 bj[4];
#pragma unroll
        for (int j = 0; j < 4; j++)
            bj[j] = *reinterpret_cast<const float2*>(biases + j * OUT_DIM + col);
#pragma unroll
        for (int mt = 0; mt < 4; mt++) {
            int r0 = mBase + wm * 64 + mt * 16 + tg;
            float be0 = 0.f, be1 = 0.f, be2 = 0.f, be3 = 0.f;
#pragma unroll
            for (int j = 0; j < 4; j++) {
                be0 += cA[mt][j] * bj[j].x;
                be1 += cA[mt][j] * bj[j].y;
                be2 += cB[mt][j] * bj[j].x;
                be3 += cB[mt][j] * bj[j].y;
            }
            float2 r01 = make_float2(acc[mt][nt][0] + be0, acc[mt][nt][1] + be1);
            float2 r23 = make_float2(acc[mt][nt][2] + be2, acc[mt][nt][3] + be3);
            *reinterpret_cast<float2*>(out + (size_t)r0 * OUT_DIM + col) = r01;
            *reinterpret_cast<float2*>(out + (size_t)(r0 + 8) * OUT_DIM + col) = r23;
        }
    }
}

// ---------------------------------------------------------------------------
// kernel_launch
// Inputs: input(f32 4096x1024), phase(f32 4096), weights(f32 4x1024x1024),
//         biases(f32 4x1024), basis(f32 4x4). Output: f32 4096x1024
// ---------------------------------------------------------------------------
extern "C" void kernel_launch(void* const* d_in, const int* in_sizes, int n_in,
                              void* d_out, int out_size)
{
    const float* x      = (const float*)d_in[0];
    const float* phase  = (const float*)d_in[1];
    const float* w      = (const float*)d_in[2];
    const float* biases = (const float*)d_in[3];
    const float* basis  = (const float*)d_in[4];
    float* out = (float*)d_out;

    static bool attr_set = false;
    if (!attr_set) {
        cudaFuncSetAttribute(gemm_kernel,
                             cudaFuncAttributeMaxDynamicSharedMemorySize,
                             SMEM_TOTAL);
        attr_set = true;
    }

    coef_kernel<<<BATCH / 256, 256>>>(phase, basis);
    split_a_kernel<<<(BATCH * IN_DIM / 4) / 256, 256>>>(x);
    split_w_kernel<<<(4 * OUT_DIM * IN_DIM / 4) / 256, 256>>>(w);

    dim3 grid(BATCH / BM, OUT_DIM / BN);  // (32, 8)
    gemm_kernel<<<grid, 256, SMEM_TOTAL>>>(biases, out);
}